// round 1
// baseline (speedup 1.0000x reference)
#include <cuda_runtime.h>

// Problem constants
#define Bb   8
#define Tt   1024
#define Cc   256
#define Hh   4
#define HDd  64
#define Ll   6
#define FCf  1024
#define OUTo 192
#define WSw  4
#define MROWS (Bb*Tt)   // 8192

// -------- scratch (no allocations allowed) --------
__device__ float g_x  [MROWS*Cc];
__device__ float g_q  [MROWS*Cc];
__device__ float g_k  [MROWS*Cc];
__device__ float g_v  [MROWS*Cc];
__device__ float g_ao [MROWS*Cc];
__device__ float g_tmp[MROWS*Cc];
__device__ float g_h  [MROWS*FCf];
__device__ float g_pwT[Cc*2*OUTo];
__device__ float g_st [MROWS*2*OUTo];

// ---------------- embedding (+ mask applied up-front) ----------------
__global__ void __launch_bounds__(256) embed_kernel(
    const float* __restrict__ emb, const int* __restrict__ toks,
    const int* __restrict__ xlen, float* __restrict__ x)
{
    int row = blockIdx.x;            // b*T + t
    int b = row >> 10, t = row & (Tt-1);
    int tok = toks[row];
    float val = (t < xlen[b]) ? emb[(size_t)tok*Cc + threadIdx.x] * 16.0f : 0.0f;
    x[(size_t)row*Cc + threadIdx.x] = val;
}

// ---------------- generic tiled fp32 GEMM: C = A(MxK) @ B(KxN) + bias ----------------
// BM=128, BN=64, BK=16, 256 threads, 8x4 microtile.
template<int RELU>
__global__ void __launch_bounds__(256) gemm_kernel(
    const float* __restrict__ A, const float* __restrict__ B,
    const float* __restrict__ bias, float* __restrict__ C,
    int M, int N, int K)
{
    __shared__ float sA[16][128];
    __shared__ float sB[16][64];
    int tid = threadIdx.x;
    int tx = tid & 15, ty = tid >> 4;
    int n0 = blockIdx.x * 64;
    int m0 = blockIdx.y * 128;

    float acc[8][4];
#pragma unroll
    for (int i = 0; i < 8; i++)
#pragma unroll
        for (int j = 0; j < 4; j++) acc[i][j] = 0.f;

    for (int kt = 0; kt < K; kt += 16) {
#pragma unroll
        for (int jj = 0; jj < 2; jj++) {
            int id  = tid + jj*256;
            int row = id >> 2;
            int kc  = (id & 3) << 2;
            float4 a = *(const float4*)(A + (size_t)(m0+row)*K + kt + kc);
            sA[kc+0][row] = a.x; sA[kc+1][row] = a.y;
            sA[kc+2][row] = a.z; sA[kc+3][row] = a.w;
        }
        {
            int row = tid >> 4;
            int c   = (tid & 15) << 2;
            *(float4*)&sB[row][c] = *(const float4*)(B + (size_t)(kt+row)*N + n0 + c);
        }
        __syncthreads();
#pragma unroll
        for (int kk = 0; kk < 16; kk++) {
            float4 a0 = *(const float4*)&sA[kk][ty*8];
            float4 a1 = *(const float4*)&sA[kk][ty*8+4];
            float4 b4 = *(const float4*)&sB[kk][tx*4];
            float av[8] = {a0.x,a0.y,a0.z,a0.w,a1.x,a1.y,a1.z,a1.w};
            float bv[4] = {b4.x,b4.y,b4.z,b4.w};
#pragma unroll
            for (int i = 0; i < 8; i++)
#pragma unroll
                for (int j = 0; j < 4; j++) acc[i][j] += av[i]*bv[j];
        }
        __syncthreads();
    }
    float bb[4];
#pragma unroll
    for (int j = 0; j < 4; j++) bb[j] = bias[n0 + tx*4 + j];
#pragma unroll
    for (int i = 0; i < 8; i++) {
        float4 r;
        r.x = acc[i][0] + bb[0];
        r.y = acc[i][1] + bb[1];
        r.z = acc[i][2] + bb[2];
        r.w = acc[i][3] + bb[3];
        if (RELU) {
            r.x = fmaxf(r.x, 0.f); r.y = fmaxf(r.y, 0.f);
            r.z = fmaxf(r.z, 0.f); r.w = fmaxf(r.w, 0.f);
        }
        *(float4*)(C + (size_t)(m0+ty*8+i)*N + n0 + tx*4) = r;
    }
}

// ---------------- flash-style attention with windowed relative bias ----------------
// One block = (b, h, 64-row q tile). 256 threads: tx in [0,16) cols, ty in [0,16) row-groups of 4.
#define ATTN_SMEM ((3*64*68 + 2*9*64) * (int)sizeof(float))

__global__ void __launch_bounds__(256) attn_kernel(
    const float* __restrict__ q, const float* __restrict__ k, const float* __restrict__ v,
    const float* __restrict__ relk, const float* __restrict__ relv,
    const int* __restrict__ xlen, float* __restrict__ o)
{
    extern __shared__ float sm[];
    float* sQt = sm;               // [64 d][68] d-major Q^T (scaled)
    float* sKP = sm + 64*68;       // K^T [64 d][68] during scores; P [64 q][68] during PV
    float* sV  = sm + 2*64*68;     // [64 c][68]
    float* sRK = sm + 3*64*68;     // [9][64]
    float* sRV = sRK + 9*64;

    int tid = threadIdx.x;
    int tx = tid & 15, ty = tid >> 4;
    int qt = blockIdx.x, h = blockIdx.y, b = blockIdx.z;
    int q0 = qt << 6;
    int len = xlen[b];

    float* obase = o + ((size_t)(b*Tt+q0))*Cc + h*HDd;
    if (q0 >= len) {   // fully masked tile -> zeros
#pragma unroll
        for (int i = 0; i < 4; i++)
            *(float4*)(obase + (size_t)(ty*4+i)*Cc + tx*4) = make_float4(0,0,0,0);
        return;
    }

    for (int i = tid; i < 9*64; i += 256) { sRK[i] = relk[i]; sRV[i] = relv[i]; }

    const float* qbase = q + ((size_t)(b*Tt+q0))*Cc + h*HDd;
#pragma unroll
    for (int e = 0; e < 4; e++) {
        int id  = tid + e*256;
        int row = id >> 4;
        int d4  = (id & 15) << 2;
        float4 a = *(const float4*)(qbase + (size_t)row*Cc + d4);
        sQt[(d4+0)*68+row] = a.x*0.125f;
        sQt[(d4+1)*68+row] = a.y*0.125f;
        sQt[(d4+2)*68+row] = a.z*0.125f;
        sQt[(d4+3)*68+row] = a.w*0.125f;
    }
    __syncthreads();

    float m_i[4], l_i[4], oacc[4][4];
#pragma unroll
    for (int i = 0; i < 4; i++) {
        m_i[i] = -1e30f; l_i[i] = 0.f;
#pragma unroll
        for (int j = 0; j < 4; j++) oacc[i][j] = 0.f;
    }

    int nkt = (len + 63) >> 6;
    for (int kt = 0; kt < nkt; kt++) {
        int k0 = kt << 6;
        const float* kbase = k + ((size_t)(b*Tt+k0))*Cc + h*HDd;
        const float* vbase = v + ((size_t)(b*Tt+k0))*Cc + h*HDd;
#pragma unroll
        for (int e = 0; e < 4; e++) {
            int id  = tid + e*256;
            int col = id >> 4;
            int d4  = (id & 15) << 2;
            float4 a = *(const float4*)(kbase + (size_t)col*Cc + d4);
            sKP[(d4+0)*68+col] = a.x;
            sKP[(d4+1)*68+col] = a.y;
            sKP[(d4+2)*68+col] = a.z;
            sKP[(d4+3)*68+col] = a.w;
            float4 vv = *(const float4*)(vbase + (size_t)col*Cc + d4);
            *(float4*)&sV[col*68 + d4] = vv;
        }
        __syncthreads();

        // scores: S = (Q*scale) @ K^T   (64x64x64 tile)
        float s[4][4];
#pragma unroll
        for (int i = 0; i < 4; i++)
#pragma unroll
            for (int j = 0; j < 4; j++) s[i][j] = 0.f;
#pragma unroll 8
        for (int d = 0; d < 64; d++) {
            float4 aq = *(const float4*)&sQt[d*68 + ty*4];
            float4 bk = *(const float4*)&sKP[d*68 + tx*4];
            float av[4] = {aq.x,aq.y,aq.z,aq.w};
            float bv[4] = {bk.x,bk.y,bk.z,bk.w};
#pragma unroll
            for (int i = 0; i < 4; i++)
#pragma unroll
                for (int j = 0; j < 4; j++) s[i][j] += av[i]*bv[j];
        }

        // windowed relative-key bias + key mask
#pragma unroll
        for (int i = 0; i < 4; i++) {
            int qg = q0 + ty*4 + i;
#pragma unroll
            for (int j = 0; j < 4; j++) {
                int kg = k0 + tx*4 + j;
                int off = kg - qg;
                if (off >= -WSw && off <= WSw) {
                    const float* rk = &sRK[(off+WSw)*64];
                    float a = 0.f;
#pragma unroll 4
                    for (int d = 0; d < 64; d++) a += sQt[d*68 + ty*4 + i] * rk[d];
                    s[i][j] += a;
                }
                if (kg >= len) s[i][j] = -1e30f;
            }
        }

        // online softmax (row groups of 16 lanes)
#pragma unroll
        for (int i = 0; i < 4; i++) {
            float mx = fmaxf(fmaxf(s[i][0], s[i][1]), fmaxf(s[i][2], s[i][3]));
            for (int ofs = 8; ofs; ofs >>= 1) mx = fmaxf(mx, __shfl_xor_sync(0xffffffffu, mx, ofs));
            float mnew = fmaxf(m_i[i], mx);
            float corr = __expf(m_i[i] - mnew);
            l_i[i] *= corr;
#pragma unroll
            for (int j = 0; j < 4; j++) oacc[i][j] *= corr;
            m_i[i] = mnew;
            float rs = 0.f;
#pragma unroll
            for (int j = 0; j < 4; j++) { float p = __expf(s[i][j] - mnew); s[i][j] = p; rs += p; }
            for (int ofs = 8; ofs; ofs >>= 1) rs += __shfl_xor_sync(0xffffffffu, rs, ofs);
            l_i[i] += rs;
        }
        __syncthreads();               // all reads of K^T done
#pragma unroll
        for (int i = 0; i < 4; i++)    // P overlays K buffer, row-major
            *(float4*)&sKP[(ty*4+i)*68 + tx*4] = make_float4(s[i][0], s[i][1], s[i][2], s[i][3]);
        __syncthreads();

        // O += P @ V
#pragma unroll 4
        for (int c = 0; c < 64; c++) {
            float4 vv = *(const float4*)&sV[c*68 + tx*4];
#pragma unroll
            for (int i = 0; i < 4; i++) {
                float p = sKP[(ty*4+i)*68 + c];
                oacc[i][0] += p*vv.x; oacc[i][1] += p*vv.y;
                oacc[i][2] += p*vv.z; oacc[i][3] += p*vv.w;
            }
        }
        // windowed relative-value contribution
#pragma unroll
        for (int i = 0; i < 4; i++) {
            int qg  = q0 + ty*4 + i;
            int clo = qg - WSw - k0; if (clo < 0)  clo = 0;
            int chi = qg + WSw - k0; if (chi > 63) chi = 63;
            for (int c = clo; c <= chi; c++) {
                float p = sKP[(ty*4+i)*68 + c];
                const float* rv = &sRV[(size_t)(k0 + c - qg + WSw)*64 + tx*4];
                oacc[i][0] += p*rv[0]; oacc[i][1] += p*rv[1];
                oacc[i][2] += p*rv[2]; oacc[i][3] += p*rv[3];
            }
        }
        __syncthreads();
    }

#pragma unroll
    for (int i = 0; i < 4; i++) {
        int row = ty*4 + i;
        float4 r4;
        if (q0 + row < len && l_i[i] > 0.f) {
            float inv = 1.f / l_i[i];
            r4 = make_float4(oacc[i][0]*inv, oacc[i][1]*inv, oacc[i][2]*inv, oacc[i][3]*inv);
        } else {
            r4 = make_float4(0,0,0,0);
        }
        *(float4*)(obase + (size_t)row*Cc + tx*4) = r4;
    }
}

// ---------------- fused residual + LayerNorm (+optional mask) ----------------
__global__ void __launch_bounds__(256) ln_kernel(
    float* __restrict__ x, const float* __restrict__ r,
    const float* __restrict__ g, const float* __restrict__ bb,
    const int* __restrict__ xlen, int domask)
{
    int row = blockIdx.x;
    int tid = threadIdx.x;
    size_t base = (size_t)row * Cc;
    float val = x[base + tid] + r[base + tid];
    __shared__ float red[8];
    __shared__ float bc;

    float s = val;
    for (int ofs = 16; ofs; ofs >>= 1) s += __shfl_xor_sync(0xffffffffu, s, ofs);
    if ((tid & 31) == 0) red[tid >> 5] = s;
    __syncthreads();
    if (tid == 0) { float t2 = 0.f; for (int i = 0; i < 8; i++) t2 += red[i]; bc = t2; }
    __syncthreads();
    float mean = bc * (1.f/256.f);
    float d = val - mean;
    s = d*d;
    for (int ofs = 16; ofs; ofs >>= 1) s += __shfl_xor_sync(0xffffffffu, s, ofs);
    if ((tid & 31) == 0) red[tid >> 5] = s;
    __syncthreads();
    if (tid == 0) { float t2 = 0.f; for (int i = 0; i < 8; i++) t2 += red[i]; bc = t2; }
    __syncthreads();
    float var = bc * (1.f/256.f);
    float out = d * rsqrtf(var + 1e-5f) * g[tid] + bb[tid];
    if (domask) {
        int b = row >> 10, t = row & (Tt-1);
        if (t >= xlen[b]) out = 0.f;
    }
    x[base + tid] = out;
}

// ---------------- small helpers ----------------
__global__ void __launch_bounds__(256) transw_kernel(const float* __restrict__ pw, float* __restrict__ pwT)
{
    int idx = blockIdx.x * 256 + threadIdx.x;   // 384*256
    int o = idx >> 8, c = idx & 255;
    pwT[(size_t)c*(2*OUTo) + o] = pw[idx];
}

__global__ void trans_out_kernel(const float* __restrict__ x, float* __restrict__ out)
{
    __shared__ float tile[32][33];
    int b = blockIdx.z, t0 = blockIdx.x*32, c0 = blockIdx.y*32;
    int tx = threadIdx.x, ty = threadIdx.y;
    for (int i = ty; i < 32; i += 8)
        tile[i][tx] = x[((size_t)(b*Tt + t0+i))*Cc + c0+tx];
    __syncthreads();
    for (int i = ty; i < 32; i += 8)
        out[((size_t)b*Cc + c0+i)*Tt + t0+tx] = tile[tx][i];
}

__global__ void stats_out_kernel(const float* __restrict__ st, const int* __restrict__ xlen,
                                 float* __restrict__ om, float* __restrict__ ol)
{
    __shared__ float tile[32][33];
    int b = blockIdx.z, t0 = blockIdx.x*32, o0 = blockIdx.y*32;
    int tx = threadIdx.x, ty = threadIdx.y;
    for (int i = ty; i < 32; i += 8)
        tile[i][tx] = st[((size_t)(b*Tt + t0+i))*(2*OUTo) + o0+tx];
    __syncthreads();
    int len = xlen[b];
    for (int i = ty; i < 32; i += 8) {
        int oo = o0 + i;
        float val = (t0+tx < len) ? tile[tx][i] : 0.f;
        if (oo < OUTo) om[((size_t)b*OUTo + oo)*Tt + t0+tx] = val;
        else           ol[((size_t)b*OUTo + (oo-OUTo))*Tt + t0+tx] = val;
    }
}

__global__ void __launch_bounds__(256) mask_out_kernel(const int* __restrict__ xlen, float* __restrict__ om)
{
    int b = blockIdx.y;
    int t = blockIdx.x * 256 + threadIdx.x;
    om[(size_t)b*Tt + t] = (t < xlen[b]) ? 1.f : 0.f;
}

// ---------------- host launcher ----------------
extern "C" void kernel_launch(void* const* d_in, const int* in_sizes, int n_in,
                              void* d_out, int out_size)
{
    (void)in_sizes; (void)n_in; (void)out_size;
    const float* emb  = (const float*)d_in[0];
    const float* Wq   = (const float*)d_in[1];
    const float* Wk   = (const float*)d_in[2];
    const float* Wv   = (const float*)d_in[3];
    const float* Wo   = (const float*)d_in[4];
    const float* bq   = (const float*)d_in[5];
    const float* bk   = (const float*)d_in[6];
    const float* bv   = (const float*)d_in[7];
    const float* bo   = (const float*)d_in[8];
    const float* relk = (const float*)d_in[9];
    const float* relv = (const float*)d_in[10];
    const float* ln1g = (const float*)d_in[11];
    const float* ln1b = (const float*)d_in[12];
    const float* ln2g = (const float*)d_in[13];
    const float* ln2b = (const float*)d_in[14];
    const float* w1   = (const float*)d_in[15];
    const float* b1   = (const float*)d_in[16];
    const float* w2   = (const float*)d_in[17];
    const float* b2   = (const float*)d_in[18];
    const float* pw   = (const float*)d_in[19];
    const float* pb   = (const float*)d_in[20];
    const int*   toks = (const int*)d_in[21];
    const int*   xlen = (const int*)d_in[22];
    float* out = (float*)d_out;

    float *x, *qb, *kb, *vb, *ao, *tmp, *hb, *pwT, *st;
    cudaGetSymbolAddress((void**)&x,   g_x);
    cudaGetSymbolAddress((void**)&qb,  g_q);
    cudaGetSymbolAddress((void**)&kb,  g_k);
    cudaGetSymbolAddress((void**)&vb,  g_v);
    cudaGetSymbolAddress((void**)&ao,  g_ao);
    cudaGetSymbolAddress((void**)&tmp, g_tmp);
    cudaGetSymbolAddress((void**)&hb,  g_h);
    cudaGetSymbolAddress((void**)&pwT, g_pwT);
    cudaGetSymbolAddress((void**)&st,  g_st);

    cudaFuncSetAttribute(attn_kernel, cudaFuncAttributeMaxDynamicSharedMemorySize, ATTN_SMEM);

    embed_kernel<<<MROWS, 256>>>(emb, toks, xlen, x);

    for (int i = 0; i < Ll; i++) {
        size_t wo = (size_t)i * Cc * Cc;
        gemm_kernel<0><<<dim3(Cc/64, MROWS/128), 256>>>(x, Wq + wo, bq + i*Cc, qb, MROWS, Cc, Cc);
        gemm_kernel<0><<<dim3(Cc/64, MROWS/128), 256>>>(x, Wk + wo, bk + i*Cc, kb, MROWS, Cc, Cc);
        gemm_kernel<0><<<dim3(Cc/64, MROWS/128), 256>>>(x, Wv + wo, bv + i*Cc, vb, MROWS, Cc, Cc);

        attn_kernel<<<dim3(Tt/64, Hh, Bb), 256, ATTN_SMEM>>>(
            qb, kb, vb, relk + (size_t)i*(2*WSw+1)*HDd, relv + (size_t)i*(2*WSw+1)*HDd, xlen, ao);

        gemm_kernel<0><<<dim3(Cc/64, MROWS/128), 256>>>(ao, Wo + wo, bo + i*Cc, tmp, MROWS, Cc, Cc);
        ln_kernel<<<MROWS, 256>>>(x, tmp, ln1g + i*Cc, ln1b + i*Cc, xlen, 0);

        size_t fo = (size_t)i * Cc * FCf;
        gemm_kernel<1><<<dim3(FCf/64, MROWS/128), 256>>>(x, w1 + fo, b1 + i*FCf, hb, MROWS, FCf, Cc);
        gemm_kernel<0><<<dim3(Cc/64, MROWS/128), 256>>>(hb, w2 + fo, b2 + i*Cc, tmp, MROWS, Cc, FCf);
        ln_kernel<<<MROWS, 256>>>(x, tmp, ln2g + i*Cc, ln2b + i*Cc, xlen, 1);
    }

    transw_kernel<<<2*OUTo, 256>>>(pw, pwT);
    gemm_kernel<0><<<dim3((2*OUTo)/64, MROWS/128), 256>>>(x, pwT, pb, st, MROWS, 2*OUTo, Cc);

    size_t off_m    = (size_t)Bb*Cc*Tt;
    size_t off_logs = off_m + (size_t)Bb*OUTo*Tt;
    size_t off_mask = off_logs + (size_t)Bb*OUTo*Tt;
    trans_out_kernel<<<dim3(Tt/32, Cc/32, Bb), dim3(32,8)>>>(x, out);
    stats_out_kernel<<<dim3(Tt/32, (2*OUTo)/32, Bb), dim3(32,8)>>>(st, xlen, out + off_m, out + off_logs);
    mask_out_kernel<<<dim3(Tt/256, Bb), 256>>>(xlen, out + off_mask);
}

// round 6
// speedup vs baseline: 1.4041x; 1.4041x over previous
#include <cuda_runtime.h>
#include <cuda_bf16.h>
#include <cstdint>

// Problem constants
#define Bb   8
#define Tt   1024
#define Cc   256
#define Hh   4
#define HDd  64
#define Ll   6
#define FCf  1024
#define OUTo 192
#define WSw  4
#define MROWS (Bb*Tt)   // 8192

// weight region offsets (elements) in transposed bf16 weight pool
#define OFF_Q  0
#define OFF_K  393216
#define OFF_V  786432
#define OFF_O  1179648
#define OFF_1  1572864
#define OFF_2  3145728
#define OFF_P  4718592
#define WT_TOT 4816896

// -------- scratch (no allocations allowed) --------
__device__ float g_x  [MROWS*Cc];
__device__ float g_q  [MROWS*Cc];
__device__ float g_k  [MROWS*Cc];
__device__ float g_v  [MROWS*Cc];
__device__ float g_ao [MROWS*Cc];
__device__ float g_tmp[MROWS*Cc];
__device__ float g_h  [MROWS*FCf];
__device__ float g_st [MROWS*2*OUTo];
__device__ __nv_bfloat16 g_wthi[WT_TOT];
__device__ __nv_bfloat16 g_wtlo[WT_TOT];
__device__ __nv_bfloat16 g_cvhi[MROWS*FCf];
__device__ __nv_bfloat16 g_cvlo[MROWS*FCf];

// ================= mma.sync helpers (valid on compute_103 base target) =================
__device__ __forceinline__ uint32_t smem_u32(const void* p) {
    uint32_t a;
    asm("{ .reg .u64 t; cvta.to.shared.u64 t, %1; cvt.u32.u64 %0, t; }" : "=r"(a) : "l"(p));
    return a;
}

#define MMA16816(d, a, b) \
    asm volatile("mma.sync.aligned.m16n8k16.row.col.f32.bf16.bf16.f32 " \
        "{%0,%1,%2,%3}, {%4,%5,%6,%7}, {%8,%9}, {%0,%1,%2,%3};" \
        : "+f"((d)[0]), "+f"((d)[1]), "+f"((d)[2]), "+f"((d)[3]) \
        : "r"((a)[0]), "r"((a)[1]), "r"((a)[2]), "r"((a)[3]), "r"((b)[0]), "r"((b)[1]))

#define CP16(dst, src) \
    asm volatile("cp.async.cg.shared.global [%0], [%1], 16;" :: "r"(dst), "l"(src))
#define CP_COMMIT() asm volatile("cp.async.commit_group;" ::: "memory")
#define CP_WAIT(n)  asm volatile("cp.async.wait_group %0;" :: "n"(n) : "memory")

// SMEM tile: 128 rows x 32 bf16 cols, padded row stride 40 elements (80 B) -> conflict-free
#define TROW 40
#define TILE_ELTS (128*TROW)          // 5120 elements
#define TILE_BYTES (TILE_ELTS*2)      // 10240 bytes
#define STAGE_BYTES (4*TILE_BYTES)    // Ahi,Alo,Bhi,Blo
#define GSM_TOTAL (2*STAGE_BYTES)     // double buffer = 81920 B

// load one 128x32 bf16 tile (gmem row-major, K stride) into padded smem via cp.async
__device__ __forceinline__ void cp_tile(uint32_t dstb, const __nv_bfloat16* src, int K, int tid) {
#pragma unroll
    for (int e = 0; e < 2; e++) {
        int id  = tid + e*256;      // 0..511
        int row = id >> 2;
        int seg = id & 3;           // 16B segment within 64B row
        uint32_t dst = dstb + row*(TROW*2) + seg*16;
        const char* s = (const char*)(src + (size_t)row*K) + seg*16;
        CP16(dst, s);
    }
}

// ================ tensor-core GEMM: C[M,N] = A[M,K] @ Bt[N,K]^T + bias ================
// A as bf16 hi/lo (row-major, K contiguous), B as bf16 hi/lo [N,K]. 3-term compensation.
template<int RELU>
__global__ void __launch_bounds__(256, 1) gemm_mma(
    const __nv_bfloat16* __restrict__ Ahi, const __nv_bfloat16* __restrict__ Alo,
    const __nv_bfloat16* __restrict__ Bhi, const __nv_bfloat16* __restrict__ Blo,
    const float* __restrict__ bias, float* __restrict__ C, int N, int K)
{
    extern __shared__ __nv_bfloat16 smb[];
    uint32_t sbase = smem_u32(smb);
    int tid = threadIdx.x, lane = tid & 31, wid = tid >> 5;
    int wm = wid >> 2, wn = wid & 3;              // 2 x 4 warp grid
    int n0 = blockIdx.x * 128, m0 = blockIdx.y * 128;
    int nk = K >> 5;

    float acc[4][4][4];
#pragma unroll
    for (int mi = 0; mi < 4; mi++)
#pragma unroll
        for (int ni = 0; ni < 4; ni++)
#pragma unroll
            for (int j = 0; j < 4; j++) acc[mi][ni][j] = 0.f;

    // prologue: stage 0
    {
        uint32_t sb = sbase;
        cp_tile(sb + 0*TILE_BYTES, Ahi + (size_t)m0*K, K, tid);
        cp_tile(sb + 1*TILE_BYTES, Alo + (size_t)m0*K, K, tid);
        cp_tile(sb + 2*TILE_BYTES, Bhi + (size_t)n0*K, K, tid);
        cp_tile(sb + 3*TILE_BYTES, Blo + (size_t)n0*K, K, tid);
        CP_COMMIT();
    }

    for (int kt = 0; kt < nk; kt++) {
        int cur = kt & 1;
        bool more = (kt + 1 < nk);
        if (more) {
            uint32_t sb = sbase + (cur ^ 1) * STAGE_BYTES;
            size_t koff = (size_t)((kt + 1) << 5);
            cp_tile(sb + 0*TILE_BYTES, Ahi + (size_t)m0*K + koff, K, tid);
            cp_tile(sb + 1*TILE_BYTES, Alo + (size_t)m0*K + koff, K, tid);
            cp_tile(sb + 2*TILE_BYTES, Bhi + (size_t)n0*K + koff, K, tid);
            cp_tile(sb + 3*TILE_BYTES, Blo + (size_t)n0*K + koff, K, tid);
            CP_COMMIT();
            CP_WAIT(1);
        } else {
            CP_WAIT(0);
        }
        __syncthreads();

        const __nv_bfloat16* sAh = smb + cur * (STAGE_BYTES/2);
        const __nv_bfloat16* sAl = sAh + TILE_ELTS;
        const __nv_bfloat16* sBh = sAh + 2*TILE_ELTS;
        const __nv_bfloat16* sBl = sAh + 3*TILE_ELTS;

#pragma unroll
        for (int kk = 0; kk < 32; kk += 16) {
            int rb = wm*64 + (lane >> 2);
            int cb = kk + (lane & 3)*2;
            uint32_t ah[4][4], al[4][4];
#pragma unroll
            for (int mi = 0; mi < 4; mi++) {
                int rr = rb + mi*16;
                ah[mi][0] = *(const uint32_t*)(sAh + rr*TROW     + cb);
                ah[mi][1] = *(const uint32_t*)(sAh + (rr+8)*TROW + cb);
                ah[mi][2] = *(const uint32_t*)(sAh + rr*TROW     + cb + 8);
                ah[mi][3] = *(const uint32_t*)(sAh + (rr+8)*TROW + cb + 8);
                al[mi][0] = *(const uint32_t*)(sAl + rr*TROW     + cb);
                al[mi][1] = *(const uint32_t*)(sAl + (rr+8)*TROW + cb);
                al[mi][2] = *(const uint32_t*)(sAl + rr*TROW     + cb + 8);
                al[mi][3] = *(const uint32_t*)(sAl + (rr+8)*TROW + cb + 8);
            }
            uint32_t bh[4][2], bl[4][2];
            int nb = wn*32 + (lane >> 2);
#pragma unroll
            for (int ni = 0; ni < 4; ni++) {
                int nn = nb + ni*8;
                bh[ni][0] = *(const uint32_t*)(sBh + nn*TROW + cb);
                bh[ni][1] = *(const uint32_t*)(sBh + nn*TROW + cb + 8);
                bl[ni][0] = *(const uint32_t*)(sBl + nn*TROW + cb);
                bl[ni][1] = *(const uint32_t*)(sBl + nn*TROW + cb + 8);
            }
#pragma unroll
            for (int mi = 0; mi < 4; mi++)
#pragma unroll
                for (int ni = 0; ni < 4; ni++) {
                    MMA16816(acc[mi][ni], ah[mi], bh[ni]);
                    MMA16816(acc[mi][ni], al[mi], bh[ni]);
                    MMA16816(acc[mi][ni], ah[mi], bl[ni]);
                }
        }
        __syncthreads();
    }

    // epilogue: d0,d1 -> row r cols c,c+1 ; d2,d3 -> row r+8
#pragma unroll
    for (int mi = 0; mi < 4; mi++) {
#pragma unroll
        for (int ni = 0; ni < 4; ni++) {
            int row = m0 + wm*64 + mi*16 + (lane >> 2);
            int col = n0 + wn*32 + ni*8 + (lane & 3)*2;
            float b0 = bias[col], b1 = bias[col+1];
            float v0 = acc[mi][ni][0] + b0, v1 = acc[mi][ni][1] + b1;
            float v2 = acc[mi][ni][2] + b0, v3 = acc[mi][ni][3] + b1;
            if (RELU) {
                v0 = fmaxf(v0, 0.f); v1 = fmaxf(v1, 0.f);
                v2 = fmaxf(v2, 0.f); v3 = fmaxf(v3, 0.f);
            }
            *(float2*)(C + (size_t)row*N + col)     = make_float2(v0, v1);
            *(float2*)(C + (size_t)(row+8)*N + col) = make_float2(v2, v3);
        }
    }
}

// ================ split-conversion kernels ================
__global__ void __launch_bounds__(256) cvt_kernel(
    const float* __restrict__ x, __nv_bfloat16* __restrict__ hi, __nv_bfloat16* __restrict__ lo)
{
    int i = blockIdx.x * 256 + threadIdx.x;
    float4 v = ((const float4*)x)[i];
    __nv_bfloat16 h0 = __float2bfloat16_rn(v.x);
    __nv_bfloat16 h1 = __float2bfloat16_rn(v.y);
    __nv_bfloat16 h2 = __float2bfloat16_rn(v.z);
    __nv_bfloat16 h3 = __float2bfloat16_rn(v.w);
    __nv_bfloat16 l0 = __float2bfloat16_rn(v.x - __bfloat162float(h0));
    __nv_bfloat16 l1 = __float2bfloat16_rn(v.y - __bfloat162float(h1));
    __nv_bfloat16 l2 = __float2bfloat16_rn(v.z - __bfloat162float(h2));
    __nv_bfloat16 l3 = __float2bfloat16_rn(v.w - __bfloat162float(h3));
    ((__nv_bfloat162*)hi)[i*2+0] = __halves2bfloat162(h0, h1);
    ((__nv_bfloat162*)hi)[i*2+1] = __halves2bfloat162(h2, h3);
    ((__nv_bfloat162*)lo)[i*2+0] = __halves2bfloat162(l0, l1);
    ((__nv_bfloat162*)lo)[i*2+1] = __halves2bfloat162(l2, l3);
}

// W [K,N] (batched over blockIdx.z, stride K*N) -> Wt hi/lo [N,K]
__global__ void cvt_wT_kernel(const float* __restrict__ W,
                              __nv_bfloat16* __restrict__ hi, __nv_bfloat16* __restrict__ lo,
                              int K, int N)
{
    __shared__ float t[32][33];
    size_t moff = (size_t)blockIdx.z * K * N;
    const float* Ws = W + moff;
    __nv_bfloat16* hs = hi + moff;
    __nv_bfloat16* ls = lo + moff;
    int n0 = blockIdx.x * 32, k0 = blockIdx.y * 32;
    int tx = threadIdx.x, ty = threadIdx.y;
    for (int i = ty; i < 32; i += 8)
        t[i][tx] = Ws[(size_t)(k0 + i) * N + n0 + tx];
    __syncthreads();
    for (int i = ty; i < 32; i += 8) {
        float v = t[tx][i];   // = W[k0+tx][n0+i]
        __nv_bfloat16 h = __float2bfloat16_rn(v);
        __nv_bfloat16 l = __float2bfloat16_rn(v - __bfloat162float(h));
        hs[(size_t)(n0 + i) * K + k0 + tx] = h;
        ls[(size_t)(n0 + i) * K + k0 + tx] = l;
    }
}

// ---------------- embedding (+ mask applied up-front) ----------------
__global__ void __launch_bounds__(256) embed_kernel(
    const float* __restrict__ emb, const int* __restrict__ toks,
    const int* __restrict__ xlen, float* __restrict__ x)
{
    int row = blockIdx.x;
    int b = row >> 10, t = row & (Tt-1);
    int tok = toks[row];
    float val = (t < xlen[b]) ? emb[(size_t)tok*Cc + threadIdx.x] * 16.0f : 0.0f;
    x[(size_t)row*Cc + threadIdx.x] = val;
}

// ---------------- flash-style attention with windowed relative bias ----------------
#define ATTN_SMEM ((3*64*68 + 2*9*64) * (int)sizeof(float))

__global__ void __launch_bounds__(256) attn_kernel(
    const float* __restrict__ q, const float* __restrict__ k, const float* __restrict__ v,
    const float* __restrict__ relk, const float* __restrict__ relv,
    const int* __restrict__ xlen, float* __restrict__ o)
{
    extern __shared__ float smf[];
    float* sQt = smf;
    float* sKP = smf + 64*68;
    float* sV  = smf + 2*64*68;
    float* sRK = smf + 3*64*68;
    float* sRV = sRK + 9*64;

    int tid = threadIdx.x;
    int tx = tid & 15, ty = tid >> 4;
    int qt = blockIdx.x, h = blockIdx.y, b = blockIdx.z;
    int q0 = qt << 6;
    int len = xlen[b];

    float* obase = o + ((size_t)(b*Tt+q0))*Cc + h*HDd;
    if (q0 >= len) {
#pragma unroll
        for (int i = 0; i < 4; i++)
            *(float4*)(obase + (size_t)(ty*4+i)*Cc + tx*4) = make_float4(0,0,0,0);
        return;
    }

    for (int i = tid; i < 9*64; i += 256) { sRK[i] = relk[i]; sRV[i] = relv[i]; }

    const float* qbase = q + ((size_t)(b*Tt+q0))*Cc + h*HDd;
#pragma unroll
    for (int e = 0; e < 4; e++) {
        int id  = tid + e*256;
        int row = id >> 4;
        int d4  = (id & 15) << 2;
        float4 a = *(const float4*)(qbase + (size_t)row*Cc + d4);
        sQt[(d4+0)*68+row] = a.x*0.125f;
        sQt[(d4+1)*68+row] = a.y*0.125f;
        sQt[(d4+2)*68+row] = a.z*0.125f;
        sQt[(d4+3)*68+row] = a.w*0.125f;
    }
    __syncthreads();

    float m_i[4], l_i[4], oacc[4][4];
#pragma unroll
    for (int i = 0; i < 4; i++) {
        m_i[i] = -1e30f; l_i[i] = 0.f;
#pragma unroll
        for (int j = 0; j < 4; j++) oacc[i][j] = 0.f;
    }

    int nkt = (len + 63) >> 6;
    for (int kt = 0; kt < nkt; kt++) {
        int k0 = kt << 6;
        const float* kbase = k + ((size_t)(b*Tt+k0))*Cc + h*HDd;
        const float* vbase = v + ((size_t)(b*Tt+k0))*Cc + h*HDd;
#pragma unroll
        for (int e = 0; e < 4; e++) {
            int id  = tid + e*256;
            int col = id >> 4;
            int d4  = (id & 15) << 2;
            float4 a = *(const float4*)(kbase + (size_t)col*Cc + d4);
            sKP[(d4+0)*68+col] = a.x;
            sKP[(d4+1)*68+col] = a.y;
            sKP[(d4+2)*68+col] = a.z;
            sKP[(d4+3)*68+col] = a.w;
            float4 vv = *(const float4*)(vbase + (size_t)col*Cc + d4);
            *(float4*)&sV[col*68 + d4] = vv;
        }
        __syncthreads();

        float s[4][4];
#pragma unroll
        for (int i = 0; i < 4; i++)
#pragma unroll
            for (int j = 0; j < 4; j++) s[i][j] = 0.f;
#pragma unroll 8
        for (int d = 0; d < 64; d++) {
            float4 aq = *(const float4*)&sQt[d*68 + ty*4];
            float4 bk = *(const float4*)&sKP[d*68 + tx*4];
            float av[4] = {aq.x,aq.y,aq.z,aq.w};
            float bv[4] = {bk.x,bk.y,bk.z,bk.w};
#pragma unroll
            for (int i = 0; i < 4; i++)
#pragma unroll
                for (int j = 0; j < 4; j++) s[i][j] += av[i]*bv[j];
        }

#pragma unroll
        for (int i = 0; i < 4; i++) {
            int qg = q0 + ty*4 + i;
#pragma unroll
            for (int j = 0; j < 4; j++) {
                int kg = k0 + tx*4 + j;
                int off = kg - qg;
                if (off >= -WSw && off <= WSw) {
                    const float* rk = &sRK[(off+WSw)*64];
                    float a = 0.f;
#pragma unroll 4
                    for (int d = 0; d < 64; d++) a += sQt[d*68 + ty*4 + i] * rk[d];
                    s[i][j] += a;
                }
                if (kg >= len) s[i][j] = -1e30f;
            }
        }

#pragma unroll
        for (int i = 0; i < 4; i++) {
            float mx = fmaxf(fmaxf(s[i][0], s[i][1]), fmaxf(s[i][2], s[i][3]));
            for (int ofs = 8; ofs; ofs >>= 1) mx = fmaxf(mx, __shfl_xor_sync(0xffffffffu, mx, ofs));
            float mnew = fmaxf(m_i[i], mx);
            float corr = __expf(m_i[i] - mnew);
            l_i[i] *= corr;
#pragma unroll
            for (int j = 0; j < 4; j++) oacc[i][j] *= corr;
            m_i[i] = mnew;
            float rs = 0.f;
#pragma unroll
            for (int j = 0; j < 4; j++) { float p = __expf(s[i][j] - mnew); s[i][j] = p; rs += p; }
            for (int ofs = 8; ofs; ofs >>= 1) rs += __shfl_xor_sync(0xffffffffu, rs, ofs);
            l_i[i] += rs;
        }
        __syncthreads();
#pragma unroll
        for (int i = 0; i < 4; i++)
            *(float4*)&sKP[(ty*4+i)*68 + tx*4] = make_float4(s[i][0], s[i][1], s[i][2], s[i][3]);
        __syncthreads();

#pragma unroll 4
        for (int c = 0; c < 64; c++) {
            float4 vv = *(const float4*)&sV[c*68 + tx*4];
#pragma unroll
            for (int i = 0; i < 4; i++) {
                float p = sKP[(ty*4+i)*68 + c];
                oacc[i][0] += p*vv.x; oacc[i][1] += p*vv.y;
                oacc[i][2] += p*vv.z; oacc[i][3] += p*vv.w;
            }
        }
#pragma unroll
        for (int i = 0; i < 4; i++) {
            int qg  = q0 + ty*4 + i;
            int clo = qg - WSw - k0; if (clo < 0)  clo = 0;
            int chi = qg + WSw - k0; if (chi > 63) chi = 63;
            for (int c = clo; c <= chi; c++) {
                float p = sKP[(ty*4+i)*68 + c];
                const float* rv = &sRV[(size_t)(k0 + c - qg + WSw)*64 + tx*4];
                oacc[i][0] += p*rv[0]; oacc[i][1] += p*rv[1];
                oacc[i][2] += p*rv[2]; oacc[i][3] += p*rv[3];
            }
        }
        __syncthreads();
    }

#pragma unroll
    for (int i = 0; i < 4; i++) {
        int row = ty*4 + i;
        float4 r4;
        if (q0 + row < len && l_i[i] > 0.f) {
            float inv = 1.f / l_i[i];
            r4 = make_float4(oacc[i][0]*inv, oacc[i][1]*inv, oacc[i][2]*inv, oacc[i][3]*inv);
        } else {
            r4 = make_float4(0,0,0,0);
        }
        *(float4*)(obase + (size_t)row*Cc + tx*4) = r4;
    }
}

// ---------------- fused residual + LayerNorm ----------------
__global__ void __launch_bounds__(256) ln_kernel(
    float* __restrict__ x, const float* __restrict__ r,
    const float* __restrict__ g, const float* __restrict__ bb,
    const int* __restrict__ xlen, int domask)
{
    int row = blockIdx.x;
    int tid = threadIdx.x;
    size_t base = (size_t)row * Cc;
    float val = x[base + tid] + r[base + tid];
    __shared__ float red[8];
    __shared__ float bc;

    float s = val;
    for (int ofs = 16; ofs; ofs >>= 1) s += __shfl_xor_sync(0xffffffffu, s, ofs);
    if ((tid & 31) == 0) red[tid >> 5] = s;
    __syncthreads();
    if (tid == 0) { float t2 = 0.f; for (int i = 0; i < 8; i++) t2 += red[i]; bc = t2; }
    __syncthreads();
    float mean = bc * (1.f/256.f);
    float d = val - mean;
    s = d*d;
    for (int ofs = 16; ofs; ofs >>= 1) s += __shfl_xor_sync(0xffffffffu, s, ofs);
    if ((tid & 31) == 0) red[tid >> 5] = s;
    __syncthreads();
    if (tid == 0) { float t2 = 0.f; for (int i = 0; i < 8; i++) t2 += red[i]; bc = t2; }
    __syncthreads();
    float var = bc * (1.f/256.f);
    float out = d * rsqrtf(var + 1e-5f) * g[tid] + bb[tid];
    if (domask) {
        int b = row >> 10, t = row & (Tt-1);
        if (t >= xlen[b]) out = 0.f;
    }
    x[base + tid] = out;
}

// ---------------- output kernels ----------------
__global__ void trans_out_kernel(const float* __restrict__ x, float* __restrict__ out)
{
    __shared__ float tile[32][33];
    int b = blockIdx.z, t0 = blockIdx.x*32, c0 = blockIdx.y*32;
    int tx = threadIdx.x, ty = threadIdx.y;
    for (int i = ty; i < 32; i += 8)
        tile[i][tx] = x[((size_t)(b*Tt + t0+i))*Cc + c0+tx];
    __syncthreads();
    for (int i = ty; i < 32; i += 8)
        out[((size_t)b*Cc + c0+i)*Tt + t0+tx] = tile[tx][i];
}

__global__ void stats_out_kernel(const float* __restrict__ st, const int* __restrict__ xlen,
                                 float* __restrict__ om, float* __restrict__ ol)
{
    __shared__ float tile[32][33];
    int b = blockIdx.z, t0 = blockIdx.x*32, o0 = blockIdx.y*32;
    int tx = threadIdx.x, ty = threadIdx.y;
    for (int i = ty; i < 32; i += 8)
        tile[i][tx] = st[((size_t)(b*Tt + t0+i))*(2*OUTo) + o0+tx];
    __syncthreads();
    int len = xlen[b];
    for (int i = ty; i < 32; i += 8) {
        int oo = o0 + i;
        float val = (t0+tx < len) ? tile[tx][i] : 0.f;
        if (oo < OUTo) om[((size_t)b*OUTo + oo)*Tt + t0+tx] = val;
        else           ol[((size_t)b*OUTo + (oo-OUTo))*Tt + t0+tx] = val;
    }
}

__global__ void __launch_bounds__(256) mask_out_kernel(const int* __restrict__ xlen, float* __restrict__ om)
{
    int b = blockIdx.y;
    int t = blockIdx.x * 256 + threadIdx.x;
    om[(size_t)b*Tt + t] = (t < xlen[b]) ? 1.f : 0.f;
}

// ---------------- host launcher ----------------
extern "C" void kernel_launch(void* const* d_in, const int* in_sizes, int n_in,
                              void* d_out, int out_size)
{
    (void)in_sizes; (void)n_in; (void)out_size;
    const float* emb  = (const float*)d_in[0];
    const float* Wq   = (const float*)d_in[1];
    const float* Wk   = (const float*)d_in[2];
    const float* Wv   = (const float*)d_in[3];
    const float* Wo   = (const float*)d_in[4];
    const float* bq   = (const float*)d_in[5];
    const float* bk   = (const float*)d_in[6];
    const float* bv   = (const float*)d_in[7];
    const float* bo   = (const float*)d_in[8];
    const float* relk = (const float*)d_in[9];
    const float* relv = (const float*)d_in[10];
    const float* ln1g = (const float*)d_in[11];
    const float* ln1b = (const float*)d_in[12];
    const float* ln2g = (const float*)d_in[13];
    const float* ln2b = (const float*)d_in[14];
    const float* w1   = (const float*)d_in[15];
    const float* b1   = (const float*)d_in[16];
    const float* w2   = (const float*)d_in[17];
    const float* b2   = (const float*)d_in[18];
    const float* pw   = (const float*)d_in[19];
    const float* pb   = (const float*)d_in[20];
    const int*   toks = (const int*)d_in[21];
    const int*   xlen = (const int*)d_in[22];
    float* out = (float*)d_out;

    float *x, *qb, *kb, *vb, *ao, *tmp, *hb, *st;
    __nv_bfloat16 *wthi, *wtlo, *cvhi, *cvlo;
    cudaGetSymbolAddress((void**)&x,    g_x);
    cudaGetSymbolAddress((void**)&qb,   g_q);
    cudaGetSymbolAddress((void**)&kb,   g_k);
    cudaGetSymbolAddress((void**)&vb,   g_v);
    cudaGetSymbolAddress((void**)&ao,   g_ao);
    cudaGetSymbolAddress((void**)&tmp,  g_tmp);
    cudaGetSymbolAddress((void**)&hb,   g_h);
    cudaGetSymbolAddress((void**)&st,   g_st);
    cudaGetSymbolAddress((void**)&wthi, g_wthi);
    cudaGetSymbolAddress((void**)&wtlo, g_wtlo);
    cudaGetSymbolAddress((void**)&cvhi, g_cvhi);
    cudaGetSymbolAddress((void**)&cvlo, g_cvlo);

    cudaFuncSetAttribute(attn_kernel, cudaFuncAttributeMaxDynamicSharedMemorySize, ATTN_SMEM);
    cudaFuncSetAttribute(gemm_mma<0>, cudaFuncAttributeMaxDynamicSharedMemorySize, GSM_TOTAL);
    cudaFuncSetAttribute(gemm_mma<1>, cudaFuncAttributeMaxDynamicSharedMemorySize, GSM_TOTAL);

    // ---- weight prep: transpose + bf16 hi/lo split ----
    cvt_wT_kernel<<<dim3(8,8,6),  dim3(32,8)>>>(Wq, wthi+OFF_Q, wtlo+OFF_Q, Cc, Cc);
    cvt_wT_kernel<<<dim3(8,8,6),  dim3(32,8)>>>(Wk, wthi+OFF_K, wtlo+OFF_K, Cc, Cc);
    cvt_wT_kernel<<<dim3(8,8,6),  dim3(32,8)>>>(Wv, wthi+OFF_V, wtlo+OFF_V, Cc, Cc);
    cvt_wT_kernel<<<dim3(8,8,6),  dim3(32,8)>>>(Wo, wthi+OFF_O, wtlo+OFF_O, Cc, Cc);
    cvt_wT_kernel<<<dim3(32,8,6), dim3(32,8)>>>(w1, wthi+OFF_1, wtlo+OFF_1, Cc, FCf);
    cvt_wT_kernel<<<dim3(8,32,6), dim3(32,8)>>>(w2, wthi+OFF_2, wtlo+OFF_2, FCf, Cc);
    cvt_kernel<<<96, 256>>>(pw, wthi+OFF_P, wtlo+OFF_P);   // already [N=384, K=256]

    embed_kernel<<<MROWS, 256>>>(emb, toks, xlen, x);

    for (int i = 0; i < Ll; i++) {
        cvt_kernel<<<2048, 256>>>(x, cvhi, cvlo);
        gemm_mma<0><<<dim3(2,64), 256, GSM_TOTAL>>>(cvhi, cvlo,
            wthi+OFF_Q+(size_t)i*65536, wtlo+OFF_Q+(size_t)i*65536, bq+i*Cc, qb, Cc, Cc);
        gemm_mma<0><<<dim3(2,64), 256, GSM_TOTAL>>>(cvhi, cvlo,
            wthi+OFF_K+(size_t)i*65536, wtlo+OFF_K+(size_t)i*65536, bk+i*Cc, kb, Cc, Cc);
        gemm_mma<0><<<dim3(2,64), 256, GSM_TOTAL>>>(cvhi, cvlo,
            wthi+OFF_V+(size_t)i*65536, wtlo+OFF_V+(size_t)i*65536, bv+i*Cc, vb, Cc, Cc);

        attn_kernel<<<dim3(Tt/64, Hh, Bb), 256, ATTN_SMEM>>>(
            qb, kb, vb, relk + (size_t)i*(2*WSw+1)*HDd, relv + (size_t)i*(2*WSw+1)*HDd, xlen, ao);

        cvt_kernel<<<2048, 256>>>(ao, cvhi, cvlo);
        gemm_mma<0><<<dim3(2,64), 256, GSM_TOTAL>>>(cvhi, cvlo,
            wthi+OFF_O+(size_t)i*65536, wtlo+OFF_O+(size_t)i*65536, bo+i*Cc, tmp, Cc, Cc);
        ln_kernel<<<MROWS, 256>>>(x, tmp, ln1g + i*Cc, ln1b + i*Cc, xlen, 0);

        cvt_kernel<<<2048, 256>>>(x, cvhi, cvlo);
        gemm_mma<1><<<dim3(8,64), 256, GSM_TOTAL>>>(cvhi, cvlo,
            wthi+OFF_1+(size_t)i*262144, wtlo+OFF_1+(size_t)i*262144, b1+i*FCf, hb, FCf, Cc);
        cvt_kernel<<<8192, 256>>>(hb, cvhi, cvlo);
        gemm_mma<0><<<dim3(2,64), 256, GSM_TOTAL>>>(cvhi, cvlo,
            wthi+OFF_2+(size_t)i*262144, wtlo+OFF_2+(size_t)i*262144, b2+i*Cc, tmp, Cc, FCf);
        ln_kernel<<<MROWS, 256>>>(x, tmp, ln2g + i*Cc, ln2b + i*Cc, xlen, 1);
    }

    cvt_kernel<<<2048, 256>>>(x, cvhi, cvlo);
    gemm_mma<0><<<dim3(3,64), 256, GSM_TOTAL>>>(cvhi, cvlo,
        wthi+OFF_P, wtlo+OFF_P, pb, st, 2*OUTo, Cc);

    size_t off_m    = (size_t)Bb*Cc*Tt;
    size_t off_logs = off_m + (size_t)Bb*OUTo*Tt;
    size_t off_mask = off_logs + (size_t)Bb*OUTo*Tt;
    trans_out_kernel<<<dim3(Tt/32, Cc/32, Bb), dim3(32,8)>>>(x, out);
    stats_out_kernel<<<dim3(Tt/32, (2*OUTo)/32, Bb), dim3(32,8)>>>(st, xlen, out + off_m, out + off_logs);
    mask_out_kernel<<<dim3(Tt/256, Bb), 256>>>(xlen, out + off_mask);
}